// round 5
// baseline (speedup 1.0000x reference)
#include <cuda_runtime.h>
#include <cstdint>

// Problem constants (fixed shapes: x = (8,16,96,96) f32, 24 steps)
#define N_ELEM 1179648   // 8*16*96*96
#define HALF   589824    // N_ELEM/2  (== 4 batches * 16 ch * 96*96)
#define HW     9216      // 96*96

typedef unsigned long long ull;

// ---------------- packed f32x2 helpers (Blackwell FFMA2 path) ----------------
__device__ __forceinline__ ull pk(float lo, float hi){ ull r; asm("mov.b64 %0,{%1,%2};":"=l"(r):"f"(lo),"f"(hi)); return r; }
__device__ __forceinline__ void upk(ull v, float&lo, float&hi){ asm("mov.b64 {%0,%1},%2;":"=f"(lo),"=f"(hi):"l"(v)); }
__device__ __forceinline__ ull fma2(ull a, ull b, ull c){ ull d; asm("fma.rn.f32x2 %0,%1,%2,%3;":"=l"(d):"l"(a),"l"(b),"l"(c)); return d; }
__device__ __forceinline__ ull add2(ull a, ull b){ ull d; asm("add.rn.f32x2 %0,%1,%2;":"=l"(d):"l"(a),"l"(b)); return d; }
__device__ __forceinline__ ull mul2(ull a, ull b){ ull d; asm("mul.rn.f32x2 %0,%1,%2;":"=l"(d):"l"(a),"l"(b)); return d; }
__device__ __forceinline__ ull sub2(ull a, ull b){ return add2(a, b ^ 0x8000000080000000ULL); }
__device__ __forceinline__ ull relu2(ull v){ float lo,hi; upk(v,lo,hi); return pk(fmaxf(lo,0.f), fmaxf(hi,0.f)); }

// ---------------- Threefry-2x32-20 (exact JAX PRNG) ----------------
__host__ __device__ __forceinline__ unsigned rotl32(unsigned x, int r){
#ifdef __CUDA_ARCH__
  return __funnelshift_l(x,x,r);
#else
  return (x<<r)|(x>>(32-r));
#endif
}
__host__ __device__ __forceinline__ void tf2x32(unsigned k0,unsigned k1,unsigned x0,unsigned x1,
                                                unsigned&o0,unsigned&o1){
  unsigned k2 = k0^k1^0x1BD11BDAu;
  x0+=k0; x1+=k1;
#define TFR(a) {x0+=x1; x1=rotl32(x1,(a)); x1^=x0;}
  TFR(13)TFR(15)TFR(26)TFR(6)   x0+=k1; x1+=k2+1u;
  TFR(17)TFR(29)TFR(16)TFR(24)  x0+=k2; x1+=k0+2u;
  TFR(13)TFR(15)TFR(26)TFR(6)   x0+=k0; x1+=k1+3u;
  TFR(17)TFR(29)TFR(16)TFR(24)  x0+=k1; x1+=k2+4u;
  TFR(13)TFR(15)TFR(26)TFR(6)   x0+=k2; x1+=k0+5u;
#undef TFR
  o0=x0; o1=x1;
}

// partitionable-mode random bits for 32-bit element i (counter hi=0, lo=i):
// bits = out0 ^ out1
__device__ __forceinline__ unsigned rbits32(unsigned k0, unsigned k1, unsigned i){
  unsigned o0,o1; tf2x32(k0,k1, 0u, i, o0,o1); return o0^o1;
}

// scratch: pre-mask updated state u = x + mask*update(x)
__device__ float g_U[N_ELEM];

// ---------------- Step kernel: perception + MLP + stochastic update ----------------
// Grid (6,6,4): 16x16 spatial tile, z = batch pair (b, b+4). Each thread = 1 pixel,
// two batches packed in f32x2 lanes. Weights pre-duplicated (w,w) in smem so each
// FFMA2 operand is one shared load.
__global__ __launch_bounds__(256,1) void ca_step(const float* __restrict__ xin,
    const float* __restrict__ w2g, const float* __restrict__ w3g,
    unsigned k0, unsigned k1)
{
  extern __shared__ ull sm[];
  ull* tile = sm;               // [16ch][18][18] packed pairs : 5184
  ull* w2s  = sm + 5184;        // [c=48][j=128] duplicated    : 6144
  ull* w3s  = w2s + 6144;       // [j=128][o=16] duplicated    : 2048
  const int tid = threadIdx.x;
  const int bp  = blockIdx.z;                 // 0..3 -> batches bp, bp+4
  const int x0p = blockIdx.x*16, y0p = blockIdx.y*16;
  const float* b0 = xin + (size_t)(bp  )*16*HW;
  const float* b1 = xin + (size_t)(bp+4)*16*HW;

  for (int idx=tid; idx<5184; idx+=256){
    int c = idx/324, r = idx-c*324, yy=r/18, xx=r-yy*18;
    int h = y0p+yy-1, w = x0p+xx-1;
    float v0=0.f, v1=0.f;
    if ((unsigned)h<96u && (unsigned)w<96u){ int off=c*HW+h*96+w; v0=b0[off]; v1=b1[off]; }
    tile[idx]=pk(v0,v1);
  }
  for (int idx=tid; idx<6144; idx+=256){     // w2 global: [j=128][c=48]
    int j=idx/48, c=idx-j*48; float v=w2g[idx]; w2s[c*128+j]=pk(v,v);
  }
  for (int idx=tid; idx<2048; idx+=256){     // w3 global: [o=16][j=128]
    int o=idx>>7, j=idx&127; float v=w3g[idx]; w3s[j*16+o]=pk(v,v);
  }
  __syncthreads();

  const int tx = tid&15, ty = tid>>4;
  const int h = y0p+ty, w = x0p+tx;

  // perception: y[3c]=identity, y[3c+1]=sobel-x, y[3c+2]=sobel-y (cross-correlation, /8)
  ull y[48];
  const ull EIGHTH = pk(0.125f,0.125f);
  #pragma unroll
  for (int c=0;c<16;c++){
    const ull* t = tile + c*324 + (ty+1)*18 + (tx+1);
    ull a=t[-19], bb=t[-18], cc=t[-17], d=t[-1], e=t[0], f=t[1], g=t[17], hh=t[18], ii=t[19];
    y[3*c]=e;
    ull sx = sub2(f,d);
    y[3*c+1]=mul2(add2(add2(sub2(cc,a),sub2(ii,g)),add2(sx,sx)),EIGHTH);
    ull sy = sub2(hh,bb);
    y[3*c+2]=mul2(add2(add2(sub2(g,a),sub2(ii,cc)),add2(sy,sy)),EIGHTH);
  }

  // stochastic update mask (jax_threefry_partitionable=True semantics):
  // element i bits = fold(threefry(key_t, (0, i))) ; mask = u > 0.5
  unsigned m0=0u, m1=0u;
  #pragma unroll 1
  for (int c=0;c<16;c++){
    unsigned i0 = (unsigned)((bp*16+c)*HW + h*96 + w);
    unsigned bits0 = rbits32(k0,k1, i0);
    unsigned bits1 = rbits32(k0,k1, i0+(unsigned)HALF);
    float u0=__uint_as_float((bits0>>9)|0x3f800000u)-1.0f;
    float u1=__uint_as_float((bits1>>9)|0x3f800000u)-1.0f;
    m0 |= (u0>0.5f)?(1u<<c):0u;
    m1 |= (u1>0.5f)?(1u<<c):0u;
  }

  // MLP: h = relu(W2 y) (128), out = W3 h (16); 4 h-outputs at a time for ILP
  ull acc[16];
  #pragma unroll
  for (int o=0;o<16;o++) acc[o]=0ull;
  #pragma unroll 1
  for (int jj=0;jj<128;jj+=4){
    ull h0=0ull,h1=0ull,h2=0ull,h3=0ull;
    #pragma unroll
    for (int c=0;c<48;c++){
      const ulonglong2* wp=(const ulonglong2*)(w2s + c*128 + jj);
      ulonglong2 wa=wp[0], wb=wp[1];
      ull yc=y[c];
      h0=fma2(yc,wa.x,h0); h1=fma2(yc,wa.y,h1);
      h2=fma2(yc,wb.x,h2); h3=fma2(yc,wb.y,h3);
    }
    h0=relu2(h0); h1=relu2(h1); h2=relu2(h2); h3=relu2(h3);
    #pragma unroll
    for (int q=0;q<4;q++){
      ull hv = (q==0)?h0 : (q==1)?h1 : (q==2)?h2 : h3;
      const ulonglong2* wp=(const ulonglong2*)(w3s + (jj+q)*16);
      #pragma unroll
      for (int o2=0;o2<8;o2++){
        ulonglong2 wv = wp[o2];
        acc[2*o2]   = fma2(hv, wv.x, acc[2*o2]);
        acc[2*o2+1] = fma2(hv, wv.y, acc[2*o2+1]);
      }
    }
  }

  // u = x + mask*update (pre-alive-mask state) -> scratch
  float* u0p = g_U + (size_t)(bp  )*16*HW + h*96 + w;
  float* u1p = g_U + (size_t)(bp+4)*16*HW + h*96 + w;
  #pragma unroll
  for (int c=0;c<16;c++){
    float xa,xb,ua,ub;
    upk(y[3*c],xa,xb);
    upk(acc[c],ua,ub);
    u0p[c*HW] = xa + (((m0>>c)&1u)? ua : 0.f);
    u1p[c*HW] = xb + (((m1>>c)&1u)? ub : 0.f);
  }
}

// ---------------- Alive-mask kernel: frames[t] = u * (alive_pre & alive_post) ----------------
__global__ __launch_bounds__(256,1) void ca_mask(const float* __restrict__ xin,
                                                 float* __restrict__ xout)
{
  int idx = blockIdx.x*256 + threadIdx.x;      // 0..73727 : (b,h,w)
  int w = idx%96; int t1 = idx/96; int h = t1%96; int b = t1/96;
  const float* ao = xin + (size_t)(b*16+3)*HW;  // old alpha (pre-update x)
  const float* an = g_U + (size_t)(b*16+3)*HW;  // new alpha (u)
  float mo=-1e30f, mn=-1e30f;
  #pragma unroll
  for (int dh=-1;dh<=1;dh++){
    int hh=h+dh; if((unsigned)hh>=96u) continue;
    #pragma unroll
    for (int dw=-1;dw<=1;dw++){
      int ww=w+dw; if((unsigned)ww>=96u) continue;
      int o=hh*96+ww;
      mo=fmaxf(mo,ao[o]); mn=fmaxf(mn,an[o]);
    }
  }
  float m = ((mo>0.1f)&&(mn>0.1f)) ? 1.0f : 0.0f;
  const float* up = g_U + (size_t)b*16*HW + h*96 + w;
  float* op = xout + (size_t)b*16*HW + h*96 + w;
  #pragma unroll
  for (int c=0;c<16;c++) op[c*HW] = m * up[c*HW];
}

// ---------------- host launcher ----------------
extern "C" void kernel_launch(void* const* d_in, const int* in_sizes, int n_in,
                              void* d_out, int out_size)
{
  const float* x=nullptr; const float* w2=nullptr; const float* w3=nullptr;
  for (int i=0;i<n_in;i++){
    if      (in_sizes[i]==N_ELEM) x =(const float*)d_in[i];
    else if (in_sizes[i]==6144)   w2=(const float*)d_in[i];
    else if (in_sizes[i]==2048)   w3=(const float*)d_in[i];
  }
  float* out=(float*)d_out;
  int T = out_size / N_ELEM;                  // 24 (avoids sync read of num_steps)
  size_t smem = (size_t)(5184+6144+2048)*sizeof(ull);   // 107008 B
  cudaFuncSetAttribute(ca_step, cudaFuncAttributeMaxDynamicSharedMemorySize, (int)smem);

  const float* xin = x;
  for (int t=0;t<T;t++){
    // key_t = threefry(base key (0,42), counter (hi=0, lo=t))
    // (jax_threefry_partitionable=True split semantics)
    unsigned k0,k1; tf2x32(0u,42u, 0u,(unsigned)t, k0,k1);
    ca_step<<<dim3(6,6,4),256,smem>>>(xin, w2, w3, k0, k1);
    ca_mask<<<288,256>>>(xin, out + (size_t)t*N_ELEM);
    xin = out + (size_t)t*N_ELEM;
  }
}